// round 8
// baseline (speedup 1.0000x reference)
#include <cuda_runtime.h>
#include <cuda_bf16.h>
#include <cuda_fp16.h>
#include <cstdint>

// DiffusionGraphConv — GB300 sm_103 (baseline PTX; no tcgen05 in this toolchain)
// Fused-overlap pipeline, take 2: GEMM smem shrunk to ONE stage (40KB) so the
// co-resident SpMM CTAs keep their occupancy (R7 failed on 80KB/CTA -> 2 CTAs/SM).
//   CSR build (4 small kernels)
//   build X0 (fp32 + fp16) + weight fold               [1 kernel]
//   P0: SpMM stage0  ||  GEMM m=0   (grid-partitioned, 1-in-17)
//   P1: SpMM stage1  ||  GEMM m=1,3
//   P2:                  GEMM m=2,4

#define NB 4096
#define BB 32
#define DD 64
#define HH 64
#define FF 128
#define EE 65536
#define SS 2
#define MM 5
#define OO 128
#define ROWLEN (BB * FF)
#define ROWLEN4 (ROWLEN / 4)

// ---- device scratch ----
__device__ float  g_X[(size_t)NB * ROWLEN];            // X0 fp32 (GEMM m=0)
__device__ __half g_Xh[(size_t)MM * NB * ROWLEN];      // [X0h,Y0,Z0,Y1,Z1] fp16
__device__ float2 g_edges[SS * EE];
__device__ int    g_off[SS * (NB + 1)];
__device__ int    g_cur[SS * NB];
__device__ int    g_cnt[SS * NB];
__device__ __nv_bfloat16 g_Wth[MM * OO * FF];          // folded, transposed [m][o][f], hi
__device__ __nv_bfloat16 g_Wtl[MM * OO * FF];          // lo

// ---------------- CSR build ----------------
__global__ void k_zero_cnt() {
    int i = blockIdx.x * blockDim.x + threadIdx.x;
    if (i < SS * NB) g_cnt[i] = 0;
}
__global__ void k_histo(const int* __restrict__ rows) {
    int i = blockIdx.x * blockDim.x + threadIdx.x;
    int s = i >> 16;
    atomicAdd(&g_cnt[s * NB + rows[i]], 1);
}
__global__ void k_scan() {
    int s = blockIdx.x;
    int t = threadIdx.x;
    __shared__ int wsum[32];
    int base = s * NB + t * 4;
    int v0 = g_cnt[base + 0], v1 = g_cnt[base + 1];
    int v2 = g_cnt[base + 2], v3 = g_cnt[base + 3];
    int tot = v0 + v1 + v2 + v3;
    int lane = t & 31, w = t >> 5;
    int x = tot;
#pragma unroll
    for (int d = 1; d < 32; d <<= 1) {
        int y = __shfl_up_sync(0xffffffffu, x, d);
        if (lane >= d) x += y;
    }
    if (lane == 31) wsum[w] = x;
    __syncthreads();
    if (w == 0) {
        int y = wsum[lane];
#pragma unroll
        for (int d = 1; d < 32; d <<= 1) {
            int z = __shfl_up_sync(0xffffffffu, y, d);
            if (lane >= d) y += z;
        }
        wsum[lane] = y;
    }
    __syncthreads();
    int excl = x - tot + (w > 0 ? wsum[w - 1] : 0);
    int ob = s * (NB + 1) + t * 4;
    g_off[ob + 0] = excl;
    g_off[ob + 1] = excl + v0;
    g_off[ob + 2] = excl + v0 + v1;
    g_off[ob + 3] = excl + v0 + v1 + v2;
    g_cur[base + 0] = excl;
    g_cur[base + 1] = excl + v0;
    g_cur[base + 2] = excl + v0 + v1;
    g_cur[base + 3] = excl + v0 + v1 + v2;
    if (t == 1023) g_off[s * (NB + 1) + NB] = excl + tot;
}
__global__ void k_scatter(const int* __restrict__ rows, const int* __restrict__ cols,
                          const float* __restrict__ vals) {
    int i = blockIdx.x * blockDim.x + threadIdx.x;
    int s = i >> 16;
    int r = rows[i];
    int p = atomicAdd(&g_cur[s * NB + r], 1);
    g_edges[s * EE + p] = make_float2(__int_as_float(cols[i]), vals[i]);
}

// ---------------- X0 build + weight fold (merged) ----------------
#define BUILD_BLOCKS ((NB * BB * 32) / 256)
__global__ void k_buildprep(const float4* __restrict__ in, const float4* __restrict__ st,
                            const float* __restrict__ w) {
    if (blockIdx.x < BUILD_BLOCKS) {
        int tid = blockIdx.x * blockDim.x + threadIdx.x;
        int q = tid & 31;
        int b = (tid >> 5) & 31;
        int n = tid >> 10;
        float4 v;
        if (q < 16)
            v = in[(size_t)b * (NB * DD / 4) + n * (DD / 4) + q];
        else
            v = st[(size_t)b * (NB * HH / 4) + n * (HH / 4) + (q - 16)];
        size_t off = (size_t)n * ROWLEN + b * FF + q * 4;
        *(float4*)(g_X + off) = v;
        __half2 h0 = __floats2half2_rn(v.x, v.y);
        __half2 h1 = __floats2half2_rn(v.z, v.w);
        uint2 u;
        u.x = *(uint32_t*)&h0;
        u.y = *(uint32_t*)&h1;
        *(uint2*)(g_Xh + off) = u;
    } else {
        int i = (blockIdx.x - BUILD_BLOCKS) * blockDim.x + threadIdx.x;  // FF*OO
        int f = i & 127;
        int o = i >> 7;
        float w0 = w[(f * MM + 0) * OO + o];
        float w1 = w[(f * MM + 1) * OO + o];
        float w2 = w[(f * MM + 2) * OO + o];
        float w3 = w[(f * MM + 3) * OO + o];
        float w4 = w[(f * MM + 4) * OO + o];
        float p[5] = {w0 - w2 - w4, w1, 2.f * w2, w3, 2.f * w4};
#pragma unroll
        for (int m = 0; m < MM; m++) {
            __nv_bfloat16 hi = __float2bfloat16_rn(p[m]);
            float lo = p[m] - __bfloat162float(hi);
            size_t idx = ((size_t)m * OO + o) * FF + f;
            g_Wth[idx] = hi;
            g_Wtl[idx] = __float2bfloat16_rn(lo);
        }
    }
}

// ---------------- MMA helpers ----------------
#define BK   32
#define BKP  40
#define TSZ  (128 * BKP)
#define STG  (4 * TSZ)
#define GEMM_SMEM (STG * 2)          // ONE stage: 40960 B (keeps SpMM occupancy)

__device__ __forceinline__ void mma_bf16(float* c, const uint32_t* a, const uint32_t* b) {
    asm volatile(
        "mma.sync.aligned.m16n8k16.row.col.f32.bf16.bf16.f32 "
        "{%0,%1,%2,%3}, {%4,%5,%6,%7}, {%8,%9}, {%0,%1,%2,%3};\n"
        : "+f"(c[0]), "+f"(c[1]), "+f"(c[2]), "+f"(c[3])
        : "r"(a[0]), "r"(a[1]), "r"(a[2]), "r"(a[3]), "r"(b[0]), "r"(b[1]));
}
__device__ __forceinline__ void ldsm_x4(uint32_t* r, uint32_t saddr) {
    asm volatile("ldmatrix.sync.aligned.m8n8.x4.shared.b16 {%0,%1,%2,%3}, [%4];"
                 : "=r"(r[0]), "=r"(r[1]), "=r"(r[2]), "=r"(r[3]) : "r"(saddr));
}

// ---------------- GEMM body (slab-parameterized, single-buffer) ----------------
__device__ __forceinline__ void gemm_body(int gbid, int m0, int m1, bool first,
                                          const float* __restrict__ biases,
                                          float* __restrict__ out,
                                          uint16_t* smx) {
    const uint32_t smem0 = (uint32_t)__cvta_generic_to_shared(smx);
    const int t = threadIdx.x;
    const int wid = t >> 5, lane = t & 31;
    const int qr = lane >> 2, qc = lane & 3;
    const int wm = wid & 1, wn = wid >> 1;

    const int bn0 = gbid * 128;
    const int n0 = bn0 & (NB - 1);
    const int b  = bn0 >> 12;

    const int ar = t >> 1, ah = t & 1;
    const int bo = t & 127, bp = t >> 7;

    const int aRowOff = (wm * 64 + (lane & 15)) * BKP + ((lane >> 4) << 3);
    const int bRowOff = (wn * 32 + ((lane >> 4) << 3) + (lane & 7)) * BKP + (lane & 8);

    const int nt = (m1 < 0) ? 4 : 8;

    float acc[4][4][4];
#pragma unroll
    for (int i = 0; i < 4; i++)
#pragma unroll
        for (int j = 0; j < 4; j++)
#pragma unroll
            for (int k = 0; k < 4; k++) acc[i][j][k] = 0.f;

    float4 aReg[4];
    uint4  bRegH[2], bRegL[2];

    auto ldg_tile = [&](int kt) {
        const int m_ = (kt < 4) ? m0 : m1;
        const int f0_ = (kt & 3) * BK;
        if (m_ == 0) {
            const float4* ap = (const float4*)(g_X +
                ((size_t)(n0 + ar) * BB + b) * FF + f0_ + ah * 16);
            aReg[0] = ap[0]; aReg[1] = ap[1]; aReg[2] = ap[2]; aReg[3] = ap[3];
        } else {
            const uint4* hp = (const uint4*)(g_Xh +
                (((size_t)m_ * NB + (n0 + ar)) * BB + b) * FF + f0_ + ah * 16);
            uint4 h0 = hp[0], h1 = hp[1];
            const __half2* u0 = (const __half2*)&h0;
            const __half2* u1 = (const __half2*)&h1;
            float2 f;
            f = __half22float2(u0[0]); aReg[0].x = f.x; aReg[0].y = f.y;
            f = __half22float2(u0[1]); aReg[0].z = f.x; aReg[0].w = f.y;
            f = __half22float2(u0[2]); aReg[1].x = f.x; aReg[1].y = f.y;
            f = __half22float2(u0[3]); aReg[1].z = f.x; aReg[1].w = f.y;
            f = __half22float2(u1[0]); aReg[2].x = f.x; aReg[2].y = f.y;
            f = __half22float2(u1[1]); aReg[2].z = f.x; aReg[2].w = f.y;
            f = __half22float2(u1[2]); aReg[3].x = f.x; aReg[3].y = f.y;
            f = __half22float2(u1[3]); aReg[3].z = f.x; aReg[3].w = f.y;
        }
        const uint4* bh = (const uint4*)(g_Wth + ((size_t)m_ * OO + bo) * FF +
                                         f0_ + bp * 16);
        const uint4* bl = (const uint4*)(g_Wtl + ((size_t)m_ * OO + bo) * FF +
                                         f0_ + bp * 16);
        bRegH[0] = bh[0]; bRegH[1] = bh[1];
        bRegL[0] = bl[0]; bRegL[1] = bl[1];
    };

    auto sts_tile = [&]() {
        uint16_t* Ah = smx;
        uint16_t* Al = Ah + TSZ;
        uint16_t* Bh = Ah + 2 * TSZ;
        uint16_t* Bl = Ah + 3 * TSZ;
        const float* av = (const float*)aReg;
        uint32_t* AhR = (uint32_t*)(Ah + ar * BKP + ah * 16);
        uint32_t* AlR = (uint32_t*)(Al + ar * BKP + ah * 16);
#pragma unroll
        for (int j = 0; j < 8; j++) {
            float x0 = av[2 * j], x1 = av[2 * j + 1];
            __nv_bfloat16 h0 = __float2bfloat16_rn(x0);
            __nv_bfloat16 h1 = __float2bfloat16_rn(x1);
            __nv_bfloat16 l0 = __float2bfloat16_rn(x0 - __bfloat162float(h0));
            __nv_bfloat16 l1 = __float2bfloat16_rn(x1 - __bfloat162float(h1));
            __nv_bfloat162 hp; hp.x = h0; hp.y = h1;
            __nv_bfloat162 lp; lp.x = l0; lp.y = l1;
            AhR[j] = *(uint32_t*)&hp;
            AlR[j] = *(uint32_t*)&lp;
        }
        uint32_t* BhR = (uint32_t*)(Bh + bo * BKP + bp * 16);
        uint32_t* BlR = (uint32_t*)(Bl + bo * BKP + bp * 16);
        const uint32_t* bhv = (const uint32_t*)bRegH;
        const uint32_t* blv = (const uint32_t*)bRegL;
#pragma unroll
        for (int j = 0; j < 8; j++) { BhR[j] = bhv[j]; BlR[j] = blv[j]; }
    };

    ldg_tile(0);
    sts_tile();
    __syncthreads();

    for (int kt = 0; kt < nt; kt++) {
        if (kt < nt - 1) ldg_tile(kt + 1);   // prefetch next tile into regs

        const uint32_t baseAh = smem0;
        const uint32_t baseAl = baseAh + TSZ * 2;
        const uint32_t baseBh = baseAh + 2 * TSZ * 2;
        const uint32_t baseBl = baseAh + 3 * TSZ * 2;

#pragma unroll
        for (int kk = 0; kk < BK; kk += 16) {
            uint32_t fbh[4][2], fbl[4][2];
#pragma unroll
            for (int p = 0; p < 2; p++) {
                uint32_t r[4];
                uint32_t off = (bRowOff + p * 16 * BKP + kk) * 2;
                ldsm_x4(r, baseBh + off);
                fbh[2 * p][0] = r[0]; fbh[2 * p][1] = r[1];
                fbh[2 * p + 1][0] = r[2]; fbh[2 * p + 1][1] = r[3];
                ldsm_x4(r, baseBl + off);
                fbl[2 * p][0] = r[0]; fbl[2 * p][1] = r[1];
                fbl[2 * p + 1][0] = r[2]; fbl[2 * p + 1][1] = r[3];
            }
#pragma unroll
            for (int mi = 0; mi < 4; mi++) {
                uint32_t fah[4], fal[4];
                uint32_t off = (aRowOff + mi * 16 * BKP + kk) * 2;
                ldsm_x4(fah, baseAh + off);
                ldsm_x4(fal, baseAl + off);
#pragma unroll
                for (int ni = 0; ni < 4; ni++) {
                    mma_bf16(acc[mi][ni], fah, fbh[ni]);
                    mma_bf16(acc[mi][ni], fah, fbl[ni]);
                    mma_bf16(acc[mi][ni], fal, fbh[ni]);
                }
            }
        }

        __syncthreads();                     // smem reads done
        if (kt < nt - 1) {
            sts_tile();                      // overwrite single buffer
            __syncthreads();
        }
    }

#pragma unroll
    for (int mi = 0; mi < 4; mi++) {
#pragma unroll
        for (int ni = 0; ni < 4; ni++) {
            int col = wn * 32 + ni * 8 + 2 * qc;
            int r0 = bn0 + wm * 64 + mi * 16 + qr;
            float* p0 = out + (size_t)r0 * OO + col;
            float* p1 = out + (size_t)(r0 + 8) * OO + col;
            float a0, a1, b0_, b1_;
            if (first) {
                a0 = biases[col]; a1 = biases[col + 1];
                b0_ = a0; b1_ = a1;
            } else {
                float2 o0 = *(float2*)p0;
                float2 o1 = *(float2*)p1;
                a0 = o0.x; a1 = o0.y; b0_ = o1.x; b1_ = o1.y;
            }
            float2 v0 = make_float2(acc[mi][ni][0] + a0, acc[mi][ni][1] + a1);
            float2 v1 = make_float2(acc[mi][ni][2] + b0_, acc[mi][ni][3] + b1_);
            *(float2*)p0 = v0;
            *(float2*)p1 = v1;
        }
    }
}

// ---------------- SpMM body (fp16 gather, half-row CTAs, 8-edge unroll) ----------------
__device__ __forceinline__ void spmm_acc8(float* acc, uint4 q, float v) {
    const __half2* h = (const __half2*)&q;
#pragma unroll
    for (int j = 0; j < 4; j++) {
        float2 f = __half22float2(h[j]);
        acc[2 * j + 0] = fmaf(v, f.x, acc[2 * j + 0]);
        acc[2 * j + 1] = fmaf(v, f.y, acc[2 * j + 1]);
    }
}

__device__ __forceinline__ void spmm_body(int stage, int sbid) {
    const int n = sbid >> 2;
    const int s = (sbid >> 1) & 1;
    const int z = sbid & 1;
    const int col = z * 256 + threadIdx.x;            // uint4 index in row [0,512)
    const int srcm = (stage == 0) ? 0 : 1 + 2 * s;
    const int dstm = (stage == 0) ? 1 + 2 * s : 2 + 2 * s;
    const uint4* src = (const uint4*)(g_Xh + (size_t)srcm * NB * ROWLEN) + col;
    uint4* dst = (uint4*)(g_Xh + (size_t)dstm * NB * ROWLEN) + (size_t)n * 512 + col;
    int e   = g_off[s * (NB + 1) + n];
    int end = g_off[s * (NB + 1) + n + 1];
    const float2* ep = g_edges + s * EE;

    float acc[8];
#pragma unroll
    for (int i = 0; i < 8; i++) acc[i] = 0.f;

    for (; e + 8 <= end; e += 8) {
        float2 cv[8];
        uint4 r[8];
#pragma unroll
        for (int i = 0; i < 8; i++) cv[i] = ep[e + i];
#pragma unroll
        for (int i = 0; i < 8; i++)
            r[i] = src[(size_t)__float_as_int(cv[i].x) * 512];
#pragma unroll
        for (int i = 0; i < 8; i++) spmm_acc8(acc, r[i], cv[i].y);
    }
    for (; e < end; e++) {
        float2 cv = ep[e];
        uint4 r = src[(size_t)__float_as_int(cv.x) * 512];
        spmm_acc8(acc, r, cv.y);
    }

    uint4 o;
    __half2* po = (__half2*)&o;
#pragma unroll
    for (int j = 0; j < 4; j++)
        po[j] = __floats2half2_rn(acc[2 * j + 0], acc[2 * j + 1]);
    *dst = o;
}

// ---------------- fused pass kernel ----------------
// pass 0: spmm stage0 || gemm m=0 (first)     grid 17408
// pass 1: spmm stage1 || gemm m=1,3 (accum)   grid 17408
// pass 2: gemm m=2,4 (accum)                  grid 1024
__global__ void __launch_bounds__(256) k_pass(int pass,
                                              const float* __restrict__ biases,
                                              float* __restrict__ out) {
    extern __shared__ uint16_t smx[];
    if (pass == 2) {
        gemm_body(blockIdx.x, 2, 4, false, biases, out, smx);
        return;
    }
    const int bid = blockIdx.x;
    const int g = bid / 17;
    if (bid - g * 17 == 0) {
        if (pass == 0) gemm_body(g, 0, -1, true, biases, out, smx);
        else           gemm_body(g, 1, 3, false, biases, out, smx);
    } else {
        spmm_body(pass, bid - g - 1);
    }
}

// ---------------- launch ----------------
extern "C" void kernel_launch(void* const* d_in, const int* in_sizes, int n_in,
                              void* d_out, int out_size) {
    const float* inputs = (const float*)d_in[0];
    const float* state  = (const float*)d_in[1];
    const int*   rows   = (const int*)d_in[2];
    const int*   cols   = (const int*)d_in[3];
    const float* vals   = (const float*)d_in[4];
    const float* weight = (const float*)d_in[5];
    const float* biases = (const float*)d_in[6];
    float* out = (float*)d_out;
    (void)in_sizes; (void)n_in; (void)out_size;

    cudaFuncSetAttribute(k_pass, cudaFuncAttributeMaxDynamicSharedMemorySize,
                         GEMM_SMEM);

    k_zero_cnt<<<(SS * NB + 255) / 256, 256>>>();
    k_histo<<<(SS * EE) / 256, 256>>>(rows);
    k_scan<<<SS, 1024>>>();
    k_scatter<<<(SS * EE) / 256, 256>>>(rows, cols, vals);
    k_buildprep<<<BUILD_BLOCKS + (FF * OO) / 256, 256>>>((const float4*)inputs,
                                                         (const float4*)state, weight);
    k_pass<<<17408, 256, GEMM_SMEM>>>(0, biases, out);
    k_pass<<<17408, 256, GEMM_SMEM>>>(1, biases, out);
    k_pass<<<1024, 256, GEMM_SMEM>>>(2, biases, out);
}

// round 9
// speedup vs baseline: 1.8567x; 1.8567x over previous
#include <cuda_runtime.h>
#include <cuda_bf16.h>
#include <cuda_fp16.h>
#include <cstdint>

// DiffusionGraphConv — GB300 sm_103 (baseline PTX; no tcgen05 in this toolchain)
// Overlap via graph-captured stream fork-join (NOT kernel fusion: R7/R8 showed
// fused grid-partitioning poisons SpMM occupancy through the shared reg alloc).
//   s0: CSR build -> buildprep -> SpMM stage0 -> SpMM stage1
//   s1:            (after prep)   GEMM m0   (after spmm0) GEMM m1,3
//                                            (after spmm1) GEMM m2,4 -> join

#define NB 4096
#define BB 32
#define DD 64
#define HH 64
#define FF 128
#define EE 65536
#define SS 2
#define MM 5
#define OO 128
#define ROWLEN (BB * FF)
#define ROWLEN4 (ROWLEN / 4)

// ---- device scratch ----
__device__ float  g_X[(size_t)NB * ROWLEN];            // X0 fp32 (GEMM m=0)
__device__ __half g_Xh[(size_t)MM * NB * ROWLEN];      // [X0h,Y0,Z0,Y1,Z1] fp16
__device__ float2 g_edges[SS * EE];
__device__ int    g_off[SS * (NB + 1)];
__device__ int    g_cur[SS * NB];
__device__ int    g_cnt[SS * NB];
__device__ __nv_bfloat16 g_Wth[MM * OO * FF];          // folded, transposed [m][o][f], hi
__device__ __nv_bfloat16 g_Wtl[MM * OO * FF];          // lo

// ---------------- CSR build ----------------
__global__ void k_zero_cnt() {
    int i = blockIdx.x * blockDim.x + threadIdx.x;
    if (i < SS * NB) g_cnt[i] = 0;
}
__global__ void k_histo(const int* __restrict__ rows) {
    int i = blockIdx.x * blockDim.x + threadIdx.x;
    int s = i >> 16;
    atomicAdd(&g_cnt[s * NB + rows[i]], 1);
}
__global__ void k_scan() {
    int s = blockIdx.x;
    int t = threadIdx.x;
    __shared__ int wsum[32];
    int base = s * NB + t * 4;
    int v0 = g_cnt[base + 0], v1 = g_cnt[base + 1];
    int v2 = g_cnt[base + 2], v3 = g_cnt[base + 3];
    int tot = v0 + v1 + v2 + v3;
    int lane = t & 31, w = t >> 5;
    int x = tot;
#pragma unroll
    for (int d = 1; d < 32; d <<= 1) {
        int y = __shfl_up_sync(0xffffffffu, x, d);
        if (lane >= d) x += y;
    }
    if (lane == 31) wsum[w] = x;
    __syncthreads();
    if (w == 0) {
        int y = wsum[lane];
#pragma unroll
        for (int d = 1; d < 32; d <<= 1) {
            int z = __shfl_up_sync(0xffffffffu, y, d);
            if (lane >= d) y += z;
        }
        wsum[lane] = y;
    }
    __syncthreads();
    int excl = x - tot + (w > 0 ? wsum[w - 1] : 0);
    int ob = s * (NB + 1) + t * 4;
    g_off[ob + 0] = excl;
    g_off[ob + 1] = excl + v0;
    g_off[ob + 2] = excl + v0 + v1;
    g_off[ob + 3] = excl + v0 + v1 + v2;
    g_cur[base + 0] = excl;
    g_cur[base + 1] = excl + v0;
    g_cur[base + 2] = excl + v0 + v1;
    g_cur[base + 3] = excl + v0 + v1 + v2;
    if (t == 1023) g_off[s * (NB + 1) + NB] = excl + tot;
}
__global__ void k_scatter(const int* __restrict__ rows, const int* __restrict__ cols,
                          const float* __restrict__ vals) {
    int i = blockIdx.x * blockDim.x + threadIdx.x;
    int s = i >> 16;
    int r = rows[i];
    int p = atomicAdd(&g_cur[s * NB + r], 1);
    g_edges[s * EE + p] = make_float2(__int_as_float(cols[i]), vals[i]);
}

// ---------------- X0 build + weight fold (merged) ----------------
#define BUILD_BLOCKS ((NB * BB * 32) / 256)
__global__ void k_buildprep(const float4* __restrict__ in, const float4* __restrict__ st,
                            const float* __restrict__ w) {
    if (blockIdx.x < BUILD_BLOCKS) {
        int tid = blockIdx.x * blockDim.x + threadIdx.x;
        int q = tid & 31;
        int b = (tid >> 5) & 31;
        int n = tid >> 10;
        float4 v;
        if (q < 16)
            v = in[(size_t)b * (NB * DD / 4) + n * (DD / 4) + q];
        else
            v = st[(size_t)b * (NB * HH / 4) + n * (HH / 4) + (q - 16)];
        size_t off = (size_t)n * ROWLEN + b * FF + q * 4;
        *(float4*)(g_X + off) = v;
        __half2 h0 = __floats2half2_rn(v.x, v.y);
        __half2 h1 = __floats2half2_rn(v.z, v.w);
        uint2 u;
        u.x = *(uint32_t*)&h0;
        u.y = *(uint32_t*)&h1;
        *(uint2*)(g_Xh + off) = u;
    } else {
        int i = (blockIdx.x - BUILD_BLOCKS) * blockDim.x + threadIdx.x;  // FF*OO
        int f = i & 127;
        int o = i >> 7;
        float w0 = w[(f * MM + 0) * OO + o];
        float w1 = w[(f * MM + 1) * OO + o];
        float w2 = w[(f * MM + 2) * OO + o];
        float w3 = w[(f * MM + 3) * OO + o];
        float w4 = w[(f * MM + 4) * OO + o];
        float p[5] = {w0 - w2 - w4, w1, 2.f * w2, w3, 2.f * w4};
#pragma unroll
        for (int m = 0; m < MM; m++) {
            __nv_bfloat16 hi = __float2bfloat16_rn(p[m]);
            float lo = p[m] - __bfloat162float(hi);
            size_t idx = ((size_t)m * OO + o) * FF + f;
            g_Wth[idx] = hi;
            g_Wtl[idx] = __float2bfloat16_rn(lo);
        }
    }
}

// ---------------- SpMM (fp16 gather, half-row CTAs, 8-edge unroll) ----------------
__device__ __forceinline__ void spmm_acc8(float* acc, uint4 q, float v) {
    const __half2* h = (const __half2*)&q;
#pragma unroll
    for (int j = 0; j < 4; j++) {
        float2 f = __half22float2(h[j]);
        acc[2 * j + 0] = fmaf(v, f.x, acc[2 * j + 0]);
        acc[2 * j + 1] = fmaf(v, f.y, acc[2 * j + 1]);
    }
}

__global__ void __launch_bounds__(256) k_spmm(int stage) {
    const int n = blockIdx.x, s = blockIdx.y;
    const int col = blockIdx.z * 256 + threadIdx.x;   // uint4 index in row [0,512)
    const int srcm = (stage == 0) ? 0 : 1 + 2 * s;
    const int dstm = (stage == 0) ? 1 + 2 * s : 2 + 2 * s;
    const uint4* src = (const uint4*)(g_Xh + (size_t)srcm * NB * ROWLEN) + col;
    uint4* dst = (uint4*)(g_Xh + (size_t)dstm * NB * ROWLEN) + (size_t)n * 512 + col;
    int e   = g_off[s * (NB + 1) + n];
    int end = g_off[s * (NB + 1) + n + 1];
    const float2* ep = g_edges + s * EE;

    float acc[8];
#pragma unroll
    for (int i = 0; i < 8; i++) acc[i] = 0.f;

    for (; e + 8 <= end; e += 8) {
        float2 cv[8];
        uint4 r[8];
#pragma unroll
        for (int i = 0; i < 8; i++) cv[i] = ep[e + i];
#pragma unroll
        for (int i = 0; i < 8; i++)
            r[i] = src[(size_t)__float_as_int(cv[i].x) * 512];
#pragma unroll
        for (int i = 0; i < 8; i++) spmm_acc8(acc, r[i], cv[i].y);
    }
    for (; e < end; e++) {
        float2 cv = ep[e];
        uint4 r = src[(size_t)__float_as_int(cv.x) * 512];
        spmm_acc8(acc, r, cv.y);
    }

    uint4 o;
    __half2* po = (__half2*)&o;
#pragma unroll
    for (int j = 0; j < 4; j++)
        po[j] = __floats2half2_rn(acc[2 * j + 0], acc[2 * j + 1]);
    *dst = o;
}

// ---------------- mma.sync bf16x3 GEMM (slab-parameterized) ----------------
#define BK   32
#define BKP  40
#define TSZ  (128 * BKP)
#define STG  (4 * TSZ)
#define GEMM_SMEM (2 * STG * 2)      // double-buffered: 81920 B (own kernel, fine)

__device__ __forceinline__ void mma_bf16(float* c, const uint32_t* a, const uint32_t* b) {
    asm volatile(
        "mma.sync.aligned.m16n8k16.row.col.f32.bf16.bf16.f32 "
        "{%0,%1,%2,%3}, {%4,%5,%6,%7}, {%8,%9}, {%0,%1,%2,%3};\n"
        : "+f"(c[0]), "+f"(c[1]), "+f"(c[2]), "+f"(c[3])
        : "r"(a[0]), "r"(a[1]), "r"(a[2]), "r"(a[3]), "r"(b[0]), "r"(b[1]));
}
__device__ __forceinline__ void ldsm_x4(uint32_t* r, uint32_t saddr) {
    asm volatile("ldmatrix.sync.aligned.m8n8.x4.shared.b16 {%0,%1,%2,%3}, [%4];"
                 : "=r"(r[0]), "=r"(r[1]), "=r"(r[2]), "=r"(r[3]) : "r"(saddr));
}

// pass 0: m=0, seed with bias.  pass 1: m=1,3 accumulate.  pass 2: m=2,4 accumulate.
__global__ void __launch_bounds__(256) k_gemm(int pass,
                                              const float* __restrict__ biases,
                                              float* __restrict__ out) {
    extern __shared__ uint16_t smx[];
    const uint32_t smem0 = (uint32_t)__cvta_generic_to_shared(smx);

    const int m0 = (pass == 0) ? 0 : (pass == 1 ? 1 : 2);
    const int m1 = (pass == 0) ? -1 : (pass == 1 ? 3 : 4);
    const bool first = (pass == 0);
    const int nt = (pass == 0) ? 4 : 8;

    const int t = threadIdx.x;
    const int wid = t >> 5, lane = t & 31;
    const int qr = lane >> 2, qc = lane & 3;
    const int wm = wid & 1, wn = wid >> 1;

    const int bn0 = blockIdx.x * 128;
    const int n0 = bn0 & (NB - 1);
    const int b  = bn0 >> 12;

    const int ar = t >> 1, ah = t & 1;
    const int bo = t & 127, bp = t >> 7;

    const int aRowOff = (wm * 64 + (lane & 15)) * BKP + ((lane >> 4) << 3);
    const int bRowOff = (wn * 32 + ((lane >> 4) << 3) + (lane & 7)) * BKP + (lane & 8);

    float acc[4][4][4];
#pragma unroll
    for (int i = 0; i < 4; i++)
#pragma unroll
        for (int j = 0; j < 4; j++)
#pragma unroll
            for (int k = 0; k < 4; k++) acc[i][j][k] = 0.f;

    float4 aReg[4];
    uint4  bRegH[2], bRegL[2];

    auto ldg_tile = [&](int kt) {
        const int m_ = (kt < 4) ? m0 : m1;
        const int f0_ = (kt & 3) * BK;
        if (m_ == 0) {
            const float4* ap = (const float4*)(g_X +
                ((size_t)(n0 + ar) * BB + b) * FF + f0_ + ah * 16);
            aReg[0] = ap[0]; aReg[1] = ap[1]; aReg[2] = ap[2]; aReg[3] = ap[3];
        } else {
            const uint4* hp = (const uint4*)(g_Xh +
                (((size_t)m_ * NB + (n0 + ar)) * BB + b) * FF + f0_ + ah * 16);
            uint4 h0 = hp[0], h1 = hp[1];
            const __half2* u0 = (const __half2*)&h0;
            const __half2* u1 = (const __half2*)&h1;
            float2 f;
            f = __half22float2(u0[0]); aReg[0].x = f.x; aReg[0].y = f.y;
            f = __half22float2(u0[1]); aReg[0].z = f.x; aReg[0].w = f.y;
            f = __half22float2(u0[2]); aReg[1].x = f.x; aReg[1].y = f.y;
            f = __half22float2(u0[3]); aReg[1].z = f.x; aReg[1].w = f.y;
            f = __half22float2(u1[0]); aReg[2].x = f.x; aReg[2].y = f.y;
            f = __half22float2(u1[1]); aReg[2].z = f.x; aReg[2].w = f.y;
            f = __half22float2(u1[2]); aReg[3].x = f.x; aReg[3].y = f.y;
            f = __half22float2(u1[3]); aReg[3].z = f.x; aReg[3].w = f.y;
        }
        const uint4* bh = (const uint4*)(g_Wth + ((size_t)m_ * OO + bo) * FF +
                                         f0_ + bp * 16);
        const uint4* bl = (const uint4*)(g_Wtl + ((size_t)m_ * OO + bo) * FF +
                                         f0_ + bp * 16);
        bRegH[0] = bh[0]; bRegH[1] = bh[1];
        bRegL[0] = bl[0]; bRegL[1] = bl[1];
    };

    auto sts_tile = [&](int st) {
        uint16_t* Ah = smx + st * STG;
        uint16_t* Al = Ah + TSZ;
        uint16_t* Bh = Ah + 2 * TSZ;
        uint16_t* Bl = Ah + 3 * TSZ;
        const float* av = (const float*)aReg;
        uint32_t* AhR = (uint32_t*)(Ah + ar * BKP + ah * 16);
        uint32_t* AlR = (uint32_t*)(Al + ar * BKP + ah * 16);
#pragma unroll
        for (int j = 0; j < 8; j++) {
            float x0 = av[2 * j], x1 = av[2 * j + 1];
            __nv_bfloat16 h0 = __float2bfloat16_rn(x0);
            __nv_bfloat16 h1 = __float2bfloat16_rn(x1);
            __nv_bfloat16 l0 = __float2bfloat16_rn(x0 - __bfloat162float(h0));
            __nv_bfloat16 l1 = __float2bfloat16_rn(x1 - __bfloat162float(h1));
            __nv_bfloat162 hp; hp.x = h0; hp.y = h1;
            __nv_bfloat162 lp; lp.x = l0; lp.y = l1;
            AhR[j] = *(uint32_t*)&hp;
            AlR[j] = *(uint32_t*)&lp;
        }
        uint32_t* BhR = (uint32_t*)(Bh + bo * BKP + bp * 16);
        uint32_t* BlR = (uint32_t*)(Bl + bo * BKP + bp * 16);
        const uint32_t* bhv = (const uint32_t*)bRegH;
        const uint32_t* blv = (const uint32_t*)bRegL;
#pragma unroll
        for (int j = 0; j < 8; j++) { BhR[j] = bhv[j]; BlR[j] = blv[j]; }
    };

    ldg_tile(0);
    sts_tile(0);
    __syncthreads();

    for (int kt = 0; kt < nt; kt++) {
        const int st = kt & 1;
        if (kt < nt - 1) ldg_tile(kt + 1);

        const uint32_t baseAh = smem0 + (st * STG) * 2;
        const uint32_t baseAl = baseAh + TSZ * 2;
        const uint32_t baseBh = baseAh + 2 * TSZ * 2;
        const uint32_t baseBl = baseAh + 3 * TSZ * 2;

#pragma unroll
        for (int kk = 0; kk < BK; kk += 16) {
            uint32_t fbh[4][2], fbl[4][2];
#pragma unroll
            for (int p = 0; p < 2; p++) {
                uint32_t r[4];
                uint32_t off = (bRowOff + p * 16 * BKP + kk) * 2;
                ldsm_x4(r, baseBh + off);
                fbh[2 * p][0] = r[0]; fbh[2 * p][1] = r[1];
                fbh[2 * p + 1][0] = r[2]; fbh[2 * p + 1][1] = r[3];
                ldsm_x4(r, baseBl + off);
                fbl[2 * p][0] = r[0]; fbl[2 * p][1] = r[1];
                fbl[2 * p + 1][0] = r[2]; fbl[2 * p + 1][1] = r[3];
            }
#pragma unroll
            for (int mi = 0; mi < 4; mi++) {
                uint32_t fah[4], fal[4];
                uint32_t off = (aRowOff + mi * 16 * BKP + kk) * 2;
                ldsm_x4(fah, baseAh + off);
                ldsm_x4(fal, baseAl + off);
#pragma unroll
                for (int ni = 0; ni < 4; ni++) {
                    mma_bf16(acc[mi][ni], fah, fbh[ni]);
                    mma_bf16(acc[mi][ni], fah, fbl[ni]);
                    mma_bf16(acc[mi][ni], fal, fbh[ni]);
                }
            }
        }

        if (kt < nt - 1) sts_tile(1 - st);
        __syncthreads();
    }

#pragma unroll
    for (int mi = 0; mi < 4; mi++) {
#pragma unroll
        for (int ni = 0; ni < 4; ni++) {
            int col = wn * 32 + ni * 8 + 2 * qc;
            int r0 = bn0 + wm * 64 + mi * 16 + qr;
            float* p0 = out + (size_t)r0 * OO + col;
            float* p1 = out + (size_t)(r0 + 8) * OO + col;
            float a0, a1, b0_, b1_;
            if (first) {
                a0 = biases[col]; a1 = biases[col + 1];
                b0_ = a0; b1_ = a1;
            } else {
                float2 o0 = *(float2*)p0;
                float2 o1 = *(float2*)p1;
                a0 = o0.x; a1 = o0.y; b0_ = o1.x; b1_ = o1.y;
            }
            float2 v0 = make_float2(acc[mi][ni][0] + a0, acc[mi][ni][1] + a1);
            float2 v1 = make_float2(acc[mi][ni][2] + b0_, acc[mi][ni][3] + b1_);
            *(float2*)p0 = v0;
            *(float2*)p1 = v1;
        }
    }
}

// ---------------- launch (fork-join inside graph capture) ----------------
extern "C" void kernel_launch(void* const* d_in, const int* in_sizes, int n_in,
                              void* d_out, int out_size) {
    const float* inputs = (const float*)d_in[0];
    const float* state  = (const float*)d_in[1];
    const int*   rows   = (const int*)d_in[2];
    const int*   cols   = (const int*)d_in[3];
    const float* vals   = (const float*)d_in[4];
    const float* weight = (const float*)d_in[5];
    const float* biases = (const float*)d_in[6];
    float* out = (float*)d_out;
    (void)in_sizes; (void)n_in; (void)out_size;

    static cudaStream_t s1 = nullptr;
    static cudaEvent_t evFork = nullptr, evS0 = nullptr, evS1 = nullptr, evJoin = nullptr;
    if (!s1) {
        cudaStreamCreateWithFlags(&s1, cudaStreamNonBlocking);
        cudaEventCreateWithFlags(&evFork, cudaEventDisableTiming);
        cudaEventCreateWithFlags(&evS0, cudaEventDisableTiming);
        cudaEventCreateWithFlags(&evS1, cudaEventDisableTiming);
        cudaEventCreateWithFlags(&evJoin, cudaEventDisableTiming);
        cudaFuncSetAttribute(k_gemm, cudaFuncAttributeMaxDynamicSharedMemorySize,
                             GEMM_SMEM);
    }

    // s0 (capture stream): CSR + build
    k_zero_cnt<<<(SS * NB + 255) / 256, 256>>>();
    k_histo<<<(SS * EE) / 256, 256>>>(rows);
    k_scan<<<SS, 1024>>>();
    k_scatter<<<(SS * EE) / 256, 256>>>(rows, cols, vals);
    k_buildprep<<<BUILD_BLOCKS + (FF * OO) / 256, 256>>>((const float4*)inputs,
                                                         (const float4*)state, weight);
    // fork: s1 starts after buildprep
    cudaEventRecord(evFork, 0);
    cudaStreamWaitEvent(s1, evFork, 0);
    k_gemm<<<(BB * NB) / 128, 256, GEMM_SMEM, s1>>>(0, biases, out);   // m0 ∥ spmm0

    k_spmm<<<dim3(NB, SS, 2), 256>>>(0);                                // stage0 on s0
    cudaEventRecord(evS0, 0);
    cudaStreamWaitEvent(s1, evS0, 0);
    k_gemm<<<(BB * NB) / 128, 256, GEMM_SMEM, s1>>>(1, biases, out);   // m1,3 ∥ spmm1

    k_spmm<<<dim3(NB, SS, 2), 256>>>(1);                                // stage1 on s0
    cudaEventRecord(evS1, 0);
    cudaStreamWaitEvent(s1, evS1, 0);
    k_gemm<<<(BB * NB) / 128, 256, GEMM_SMEM, s1>>>(2, biases, out);   // m2,4

    // join
    cudaEventRecord(evJoin, s1);
    cudaStreamWaitEvent(0, evJoin, 0);
}

// round 10
// speedup vs baseline: 2.1932x; 1.1812x over previous
#include <cuda_runtime.h>
#include <cuda_bf16.h>
#include <cuda_fp16.h>
#include <cstdint>

// DiffusionGraphConv — GB300 sm_103 (baseline PTX; no tcgen05 in this toolchain)
// Serial pipeline (overlap falsified in R7-R9). SpMM inner loop rebuilt:
//   - edge list staged in smem once per CTA (kills redundant descriptor LDGs)
//   - fp16 HFMA2 accumulation, dual accumulator sets (kills cvt overhead)
//   1) CSR build                                   ~25us
//   2) X0 build fp32+fp16 + weight fold            ~25us
//   3) SpMM x2 launches (both supports each)       ~target 180-220us
//   4) GEMM bf16x3 mma.sync + ldmatrix             ~115us

#define NB 4096
#define BB 32
#define DD 64
#define HH 64
#define FF 128
#define EE 65536
#define SS 2
#define MM 5
#define OO 128
#define ROWLEN (BB * FF)
#define ROWLEN4 (ROWLEN / 4)

// ---- device scratch ----
__device__ float  g_X[(size_t)NB * ROWLEN];            // X0 fp32 (GEMM m=0)
__device__ __half g_Xh[(size_t)MM * NB * ROWLEN];      // [X0h,Y0,Z0,Y1,Z1] fp16
__device__ float2 g_edges[SS * EE];
__device__ int    g_off[SS * (NB + 1)];
__device__ int    g_cur[SS * NB];
__device__ int    g_cnt[SS * NB];
__device__ __nv_bfloat16 g_Wth[MM * OO * FF];          // folded, transposed [m][o][f], hi
__device__ __nv_bfloat16 g_Wtl[MM * OO * FF];          // lo

// ---------------- CSR build ----------------
__global__ void k_zero_cnt() {
    int i = blockIdx.x * blockDim.x + threadIdx.x;
    if (i < SS * NB) g_cnt[i] = 0;
}
__global__ void k_histo(const int* __restrict__ rows) {
    int i = blockIdx.x * blockDim.x + threadIdx.x;
    int s = i >> 16;
    atomicAdd(&g_cnt[s * NB + rows[i]], 1);
}
__global__ void k_scan() {
    int s = blockIdx.x;
    int t = threadIdx.x;
    __shared__ int wsum[32];
    int base = s * NB + t * 4;
    int v0 = g_cnt[base + 0], v1 = g_cnt[base + 1];
    int v2 = g_cnt[base + 2], v3 = g_cnt[base + 3];
    int tot = v0 + v1 + v2 + v3;
    int lane = t & 31, w = t >> 5;
    int x = tot;
#pragma unroll
    for (int d = 1; d < 32; d <<= 1) {
        int y = __shfl_up_sync(0xffffffffu, x, d);
        if (lane >= d) x += y;
    }
    if (lane == 31) wsum[w] = x;
    __syncthreads();
    if (w == 0) {
        int y = wsum[lane];
#pragma unroll
        for (int d = 1; d < 32; d <<= 1) {
            int z = __shfl_up_sync(0xffffffffu, y, d);
            if (lane >= d) y += z;
        }
        wsum[lane] = y;
    }
    __syncthreads();
    int excl = x - tot + (w > 0 ? wsum[w - 1] : 0);
    int ob = s * (NB + 1) + t * 4;
    g_off[ob + 0] = excl;
    g_off[ob + 1] = excl + v0;
    g_off[ob + 2] = excl + v0 + v1;
    g_off[ob + 3] = excl + v0 + v1 + v2;
    g_cur[base + 0] = excl;
    g_cur[base + 1] = excl + v0;
    g_cur[base + 2] = excl + v0 + v1;
    g_cur[base + 3] = excl + v0 + v1 + v2;
    if (t == 1023) g_off[s * (NB + 1) + NB] = excl + tot;
}
__global__ void k_scatter(const int* __restrict__ rows, const int* __restrict__ cols,
                          const float* __restrict__ vals) {
    int i = blockIdx.x * blockDim.x + threadIdx.x;
    int s = i >> 16;
    int r = rows[i];
    int p = atomicAdd(&g_cur[s * NB + r], 1);
    g_edges[s * EE + p] = make_float2(__int_as_float(cols[i]), vals[i]);
}

// ---------------- X0 build + weight fold (merged) ----------------
#define BUILD_BLOCKS ((NB * BB * 32) / 256)
__global__ void k_buildprep(const float4* __restrict__ in, const float4* __restrict__ st,
                            const float* __restrict__ w) {
    if (blockIdx.x < BUILD_BLOCKS) {
        int tid = blockIdx.x * blockDim.x + threadIdx.x;
        int q = tid & 31;
        int b = (tid >> 5) & 31;
        int n = tid >> 10;
        float4 v;
        if (q < 16)
            v = in[(size_t)b * (NB * DD / 4) + n * (DD / 4) + q];
        else
            v = st[(size_t)b * (NB * HH / 4) + n * (HH / 4) + (q - 16)];
        size_t off = (size_t)n * ROWLEN + b * FF + q * 4;
        *(float4*)(g_X + off) = v;
        __half2 h0 = __floats2half2_rn(v.x, v.y);
        __half2 h1 = __floats2half2_rn(v.z, v.w);
        uint2 u;
        u.x = *(uint32_t*)&h0;
        u.y = *(uint32_t*)&h1;
        *(uint2*)(g_Xh + off) = u;
    } else {
        int i = (blockIdx.x - BUILD_BLOCKS) * blockDim.x + threadIdx.x;  // FF*OO
        int f = i & 127;
        int o = i >> 7;
        float w0 = w[(f * MM + 0) * OO + o];
        float w1 = w[(f * MM + 1) * OO + o];
        float w2 = w[(f * MM + 2) * OO + o];
        float w3 = w[(f * MM + 3) * OO + o];
        float w4 = w[(f * MM + 4) * OO + o];
        float p[5] = {w0 - w2 - w4, w1, 2.f * w2, w3, 2.f * w4};
#pragma unroll
        for (int m = 0; m < MM; m++) {
            __nv_bfloat16 hi = __float2bfloat16_rn(p[m]);
            float lo = p[m] - __bfloat162float(hi);
            size_t idx = ((size_t)m * OO + o) * FF + f;
            g_Wth[idx] = hi;
            g_Wtl[idx] = __float2bfloat16_rn(lo);
        }
    }
}

// ---------------- SpMM: smem-staged edges, HFMA2 dual accumulators ----------------
#define ECHUNK 128

__global__ void __launch_bounds__(256) k_spmm(int stage) {
    __shared__ uint2 sedge[ECHUNK];                   // {col, half2(v)}
    const int n = blockIdx.x, s = blockIdx.y;
    const int col = blockIdx.z * 256 + threadIdx.x;   // uint4 index in row [0,512)
    const int srcm = (stage == 0) ? 0 : 1 + 2 * s;
    const int dstm = (stage == 0) ? 1 + 2 * s : 2 + 2 * s;
    const uint4* src = (const uint4*)(g_Xh + (size_t)srcm * NB * ROWLEN) + col;
    uint4* dst = (uint4*)(g_Xh + (size_t)dstm * NB * ROWLEN) + (size_t)n * 512 + col;
    const int e0  = g_off[s * (NB + 1) + n];
    const int end = g_off[s * (NB + 1) + n + 1];
    const float2* ep = g_edges + s * EE;

    __half2 accE[4], accO[4];
    const __half2 z2 = __floats2half2_rn(0.f, 0.f);
#pragma unroll
    for (int j = 0; j < 4; j++) { accE[j] = z2; accO[j] = z2; }

    for (int base = e0; base < end; base += ECHUNK) {
        const int cnt = min(ECHUNK, end - base);
        if (base > e0) __syncthreads();               // protect smem reuse
        if (threadIdx.x < cnt) {
            float2 cv = ep[base + threadIdx.x];
            __half2 vh = __half2half2(__float2half_rn(cv.y));
            sedge[threadIdx.x] = make_uint2((uint32_t)__float_as_int(cv.x),
                                            *(uint32_t*)&vh);
        }
        __syncthreads();

        int i = 0;
        for (; i + 8 <= cnt; i += 8) {
            uint2 se[8];
#pragma unroll
            for (int k = 0; k < 8; k++) se[k] = sedge[i + k];
            uint4 r[8];
#pragma unroll
            for (int k = 0; k < 8; k++)
                r[k] = src[(size_t)se[k].x * 512];
#pragma unroll
            for (int k = 0; k < 8; k++) {
                __half2 vh = *(__half2*)&se[k].y;
                const __half2* h = (const __half2*)&r[k];
                __half2* acc = (k & 1) ? accO : accE;
#pragma unroll
                for (int j = 0; j < 4; j++)
                    acc[j] = __hfma2(vh, h[j], acc[j]);
            }
        }
        for (; i < cnt; i++) {
            uint2 se = sedge[i];
            uint4 r = src[(size_t)se.x * 512];
            __half2 vh = *(__half2*)&se.y;
            const __half2* h = (const __half2*)&r;
#pragma unroll
            for (int j = 0; j < 4; j++)
                accE[j] = __hfma2(vh, h[j], accE[j]);
        }
    }

    uint4 o;
    __half2* po = (__half2*)&o;
#pragma unroll
    for (int j = 0; j < 4; j++) {
        float2 fe = __half22float2(accE[j]);
        float2 fo = __half22float2(accO[j]);
        po[j] = __floats2half2_rn(fe.x + fo.x, fe.y + fo.y);
    }
    *dst = o;
}

// ---------------- mma.sync bf16x3 GEMM with ldmatrix fragments (R6) ----------------
#define BK   32
#define BKP  40
#define TSZ  (128 * BKP)
#define STG  (4 * TSZ)
#define GEMM_SMEM (2 * STG * 2)      // 81920 B

__device__ __forceinline__ void mma_bf16(float* c, const uint32_t* a, const uint32_t* b) {
    asm volatile(
        "mma.sync.aligned.m16n8k16.row.col.f32.bf16.bf16.f32 "
        "{%0,%1,%2,%3}, {%4,%5,%6,%7}, {%8,%9}, {%0,%1,%2,%3};\n"
        : "+f"(c[0]), "+f"(c[1]), "+f"(c[2]), "+f"(c[3])
        : "r"(a[0]), "r"(a[1]), "r"(a[2]), "r"(a[3]), "r"(b[0]), "r"(b[1]));
}
__device__ __forceinline__ void ldsm_x4(uint32_t* r, uint32_t saddr) {
    asm volatile("ldmatrix.sync.aligned.m8n8.x4.shared.b16 {%0,%1,%2,%3}, [%4];"
                 : "=r"(r[0]), "=r"(r[1]), "=r"(r[2]), "=r"(r[3]) : "r"(saddr));
}

__global__ void __launch_bounds__(256) k_gemm_mma(const float* __restrict__ biases,
                                                  float* __restrict__ out) {
    extern __shared__ uint16_t smx[];   // [2][Ah|Al|Bh|Bl][128][BKP]
    const uint32_t smem0 = (uint32_t)__cvta_generic_to_shared(smx);

    const int t = threadIdx.x;
    const int wid = t >> 5, lane = t & 31;
    const int qr = lane >> 2, qc = lane & 3;
    const int wm = wid & 1, wn = wid >> 1;

    const int bn0 = blockIdx.x * 128;
    const int n0 = bn0 & (NB - 1);
    const int b  = bn0 >> 12;

    const int ar = t >> 1, ah = t & 1;   // A ldg: row, 16-elem half
    const int bo = t & 127, bp = t >> 7; // B ldg: o row, 16-bf16 part

    const int aRowOff = (wm * 64 + (lane & 15)) * BKP + ((lane >> 4) << 3);
    const int bRowOff = (wn * 32 + ((lane >> 4) << 3) + (lane & 7)) * BKP + (lane & 8);

    float acc[4][4][4];
#pragma unroll
    for (int i = 0; i < 4; i++)
#pragma unroll
        for (int j = 0; j < 4; j++)
#pragma unroll
            for (int k = 0; k < 4; k++) acc[i][j][k] = 0.f;

    float4 aReg[4];
    uint4  bRegH[2], bRegL[2];

#define LDG_TILE(kt)                                                              \
    {                                                                             \
        const int m_ = (kt) >> 2, f0_ = ((kt) & 3) * BK;                          \
        if (m_ == 0) {                                                            \
            const float4* ap = (const float4*)(g_X +                              \
                ((size_t)(n0 + ar) * BB + b) * FF + f0_ + ah * 16);               \
            aReg[0] = ap[0]; aReg[1] = ap[1]; aReg[2] = ap[2]; aReg[3] = ap[3];   \
        } else {                                                                  \
            const uint4* hp = (const uint4*)(g_Xh +                               \
                (((size_t)m_ * NB + (n0 + ar)) * BB + b) * FF + f0_ + ah * 16);   \
            uint4 h0 = hp[0], h1 = hp[1];                                         \
            const __half2* u0 = (const __half2*)&h0;                              \
            const __half2* u1 = (const __half2*)&h1;                              \
            float2 f;                                                             \
            f = __half22float2(u0[0]); aReg[0].x = f.x; aReg[0].y = f.y;          \
            f = __half22float2(u0[1]); aReg[0].z = f.x; aReg[0].w = f.y;          \
            f = __half22float2(u0[2]); aReg[1].x = f.x; aReg[1].y = f.y;          \
            f = __half22float2(u0[3]); aReg[1].z = f.x; aReg[1].w = f.y;          \
            f = __half22float2(u1[0]); aReg[2].x = f.x; aReg[2].y = f.y;          \
            f = __half22float2(u1[1]); aReg[2].z = f.x; aReg[2].w = f.y;          \
            f = __half22float2(u1[2]); aReg[3].x = f.x; aReg[3].y = f.y;          \
            f = __half22float2(u1[3]); aReg[3].z = f.x; aReg[3].w = f.y;          \
        }                                                                         \
        const uint4* bh = (const uint4*)(g_Wth + ((size_t)m_ * OO + bo) * FF +    \
                                         f0_ + bp * 16);                          \
        const uint4* bl = (const uint4*)(g_Wtl + ((size_t)m_ * OO + bo) * FF +    \
                                         f0_ + bp * 16);                          \
        bRegH[0] = bh[0]; bRegH[1] = bh[1];                                       \
        bRegL[0] = bl[0]; bRegL[1] = bl[1];                                       \
    }

#define STS_TILE(st)                                                              \
    {                                                                             \
        uint16_t* Ah = smx + (st) * STG;                                          \
        uint16_t* Al = Ah + TSZ;                                                  \
        uint16_t* Bh = Ah + 2 * TSZ;                                              \
        uint16_t* Bl = Ah + 3 * TSZ;                                              \
        const float* av = (const float*)aReg;                                     \
        uint32_t* AhR = (uint32_t*)(Ah + ar * BKP + ah * 16);                     \
        uint32_t* AlR = (uint32_t*)(Al + ar * BKP + ah * 16);                     \
        _Pragma("unroll")                                                         \
        for (int j = 0; j < 8; j++) {                                             \
            float x0 = av[2 * j], x1 = av[2 * j + 1];                             \
            __nv_bfloat16 h0 = __float2bfloat16_rn(x0);                           \
            __nv_bfloat16 h1 = __float2bfloat16_rn(x1);                           \
            __nv_bfloat16 l0 = __float2bfloat16_rn(x0 - __bfloat162float(h0));    \
            __nv_bfloat16 l1 = __float2bfloat16_rn(x1 - __bfloat162float(h1));    \
            __nv_bfloat162 hp; hp.x = h0; hp.y = h1;                              \
            __nv_bfloat162 lp; lp.x = l0; lp.y = l1;                              \
            AhR[j] = *(uint32_t*)&hp;                                             \
            AlR[j] = *(uint32_t*)&lp;                                             \
        }                                                                         \
        uint32_t* BhR = (uint32_t*)(Bh + bo * BKP + bp * 16);                     \
        uint32_t* BlR = (uint32_t*)(Bl + bo * BKP + bp * 16);                     \
        const uint32_t* bhv = (const uint32_t*)bRegH;                             \
        const uint32_t* blv = (const uint32_t*)bRegL;                             \
        _Pragma("unroll")                                                         \
        for (int j = 0; j < 8; j++) { BhR[j] = bhv[j]; BlR[j] = blv[j]; }         \
    }

    LDG_TILE(0);
    STS_TILE(0);
    __syncthreads();

    for (int kt = 0; kt < 20; kt++) {
        const int st = kt & 1;
        if (kt < 19) LDG_TILE(kt + 1);

        const uint32_t baseAh = smem0 + (st * STG) * 2;
        const uint32_t baseAl = baseAh + TSZ * 2;
        const uint32_t baseBh = baseAh + 2 * TSZ * 2;
        const uint32_t baseBl = baseAh + 3 * TSZ * 2;

#pragma unroll
        for (int kk = 0; kk < BK; kk += 16) {
            uint32_t fbh[4][2], fbl[4][2];
#pragma unroll
            for (int p = 0; p < 2; p++) {
                uint32_t r[4];
                uint32_t off = (bRowOff + p * 16 * BKP + kk) * 2;
                ldsm_x4(r, baseBh + off);
                fbh[2 * p][0] = r[0]; fbh[2 * p][1] = r[1];
                fbh[2 * p + 1][0] = r[2]; fbh[2 * p + 1][1] = r[3];
                ldsm_x4(r, baseBl + off);
                fbl[2 * p][0] = r[0]; fbl[2 * p][1] = r[1];
                fbl[2 * p + 1][0] = r[2]; fbl[2 * p + 1][1] = r[3];
            }
#pragma unroll
            for (int mi = 0; mi < 4; mi++) {
                uint32_t fah[4], fal[4];
                uint32_t off = (aRowOff + mi * 16 * BKP + kk) * 2;
                ldsm_x4(fah, baseAh + off);
                ldsm_x4(fal, baseAl + off);
#pragma unroll
                for (int ni = 0; ni < 4; ni++) {
                    mma_bf16(acc[mi][ni], fah, fbh[ni]);
                    mma_bf16(acc[mi][ni], fah, fbl[ni]);
                    mma_bf16(acc[mi][ni], fal, fbh[ni]);
                }
            }
        }

        if (kt < 19) {
            STS_TILE(1 - st);
        }
        __syncthreads();
    }

#pragma unroll
    for (int mi = 0; mi < 4; mi++) {
#pragma unroll
        for (int ni = 0; ni < 4; ni++) {
            int col = wn * 32 + ni * 8 + 2 * qc;
            float b0 = biases[col], b1 = biases[col + 1];
            int r0 = bn0 + wm * 64 + mi * 16 + qr;
            float2 v0 = make_float2(acc[mi][ni][0] + b0, acc[mi][ni][1] + b1);
            float2 v1 = make_float2(acc[mi][ni][2] + b0, acc[mi][ni][3] + b1);
            *(float2*)(out + (size_t)r0 * OO + col)       = v0;
            *(float2*)(out + (size_t)(r0 + 8) * OO + col) = v1;
        }
    }
#undef LDG_TILE
#undef STS_TILE
}

// ---------------- launch (serial, R6 structure) ----------------
extern "C" void kernel_launch(void* const* d_in, const int* in_sizes, int n_in,
                              void* d_out, int out_size) {
    const float* inputs = (const float*)d_in[0];
    const float* state  = (const float*)d_in[1];
    const int*   rows   = (const int*)d_in[2];
    const int*   cols   = (const int*)d_in[3];
    const float* vals   = (const float*)d_in[4];
    const float* weight = (const float*)d_in[5];
    const float* biases = (const float*)d_in[6];
    float* out = (float*)d_out;
    (void)in_sizes; (void)n_in; (void)out_size;

    cudaFuncSetAttribute(k_gemm_mma, cudaFuncAttributeMaxDynamicSharedMemorySize,
                         GEMM_SMEM);

    k_zero_cnt<<<(SS * NB + 255) / 256, 256>>>();
    k_histo<<<(SS * EE) / 256, 256>>>(rows);
    k_scan<<<SS, 1024>>>();
    k_scatter<<<(SS * EE) / 256, 256>>>(rows, cols, vals);
    k_buildprep<<<BUILD_BLOCKS + (FF * OO) / 256, 256>>>((const float4*)inputs,
                                                         (const float4*)state, weight);
    k_spmm<<<dim3(NB, SS, 2), 256>>>(0);
    k_spmm<<<dim3(NB, SS, 2), 256>>>(1);
    k_gemm_mma<<<(BB * NB) / 128, 256, GEMM_SMEM>>>(biases, out);
}

// round 11
// speedup vs baseline: 2.7898x; 1.2720x over previous
#include <cuda_runtime.h>
#include <cuda_bf16.h>
#include <cuda_fp16.h>
#include <cstdint>

// DiffusionGraphConv — GB300 sm_103 (baseline PTX; no tcgen05 in this toolchain)
// Serial pipeline (overlap falsified R7-R9; SpMM at L2-BW ceiling R5/R6/R10).
//   1) CSR build                                   ~25us
//   2) X0 build fp32+fp16 + weight fold            ~25us
//   3) SpMM x2 (smem edges, HFMA2)                 ~280us (L2-BW floor)
//   4) GEMM: m=0 bf16x3, m=1..4 native fp16 MMA    ~65us

#define NB 4096
#define BB 32
#define DD 64
#define HH 64
#define FF 128
#define EE 65536
#define SS 2
#define MM 5
#define OO 128
#define ROWLEN (BB * FF)
#define ROWLEN4 (ROWLEN / 4)

// ---- device scratch ----
__device__ float  g_X[(size_t)NB * ROWLEN];            // X0 fp32 (GEMM m=0)
__device__ __half g_Xh[(size_t)MM * NB * ROWLEN];      // [X0h,Y0,Z0,Y1,Z1] fp16
__device__ float2 g_edges[SS * EE];
__device__ int    g_off[SS * (NB + 1)];
__device__ int    g_cur[SS * NB];
__device__ int    g_cnt[SS * NB];
__device__ __nv_bfloat16 g_Wth[MM * OO * FF];          // folded, transposed, bf16 hi (m=0 use)
__device__ __nv_bfloat16 g_Wtl[MM * OO * FF];          // bf16 lo (m=0 use)
__device__ __half g_Whf[MM * OO * FF];                 // fp16 weights (m>=1 use)

// ---------------- CSR build ----------------
__global__ void k_zero_cnt() {
    int i = blockIdx.x * blockDim.x + threadIdx.x;
    if (i < SS * NB) g_cnt[i] = 0;
}
__global__ void k_histo(const int* __restrict__ rows) {
    int i = blockIdx.x * blockDim.x + threadIdx.x;
    int s = i >> 16;
    atomicAdd(&g_cnt[s * NB + rows[i]], 1);
}
__global__ void k_scan() {
    int s = blockIdx.x;
    int t = threadIdx.x;
    __shared__ int wsum[32];
    int base = s * NB + t * 4;
    int v0 = g_cnt[base + 0], v1 = g_cnt[base + 1];
    int v2 = g_cnt[base + 2], v3 = g_cnt[base + 3];
    int tot = v0 + v1 + v2 + v3;
    int lane = t & 31, w = t >> 5;
    int x = tot;
#pragma unroll
    for (int d = 1; d < 32; d <<= 1) {
        int y = __shfl_up_sync(0xffffffffu, x, d);
        if (lane >= d) x += y;
    }
    if (lane == 31) wsum[w] = x;
    __syncthreads();
    if (w == 0) {
        int y = wsum[lane];
#pragma unroll
        for (int d = 1; d < 32; d <<= 1) {
            int z = __shfl_up_sync(0xffffffffu, y, d);
            if (lane >= d) y += z;
        }
        wsum[lane] = y;
    }
    __syncthreads();
    int excl = x - tot + (w > 0 ? wsum[w - 1] : 0);
    int ob = s * (NB + 1) + t * 4;
    g_off[ob + 0] = excl;
    g_off[ob + 1] = excl + v0;
    g_off[ob + 2] = excl + v0 + v1;
    g_off[ob + 3] = excl + v0 + v1 + v2;
    g_cur[base + 0] = excl;
    g_cur[base + 1] = excl + v0;
    g_cur[base + 2] = excl + v0 + v1;
    g_cur[base + 3] = excl + v0 + v1 + v2;
    if (t == 1023) g_off[s * (NB + 1) + NB] = excl + tot;
}
__global__ void k_scatter(const int* __restrict__ rows, const int* __restrict__ cols,
                          const float* __restrict__ vals) {
    int i = blockIdx.x * blockDim.x + threadIdx.x;
    int s = i >> 16;
    int r = rows[i];
    int p = atomicAdd(&g_cur[s * NB + r], 1);
    g_edges[s * EE + p] = make_float2(__int_as_float(cols[i]), vals[i]);
}

// ---------------- X0 build + weight fold (merged) ----------------
#define BUILD_BLOCKS ((NB * BB * 32) / 256)
__global__ void k_buildprep(const float4* __restrict__ in, const float4* __restrict__ st,
                            const float* __restrict__ w) {
    if (blockIdx.x < BUILD_BLOCKS) {
        int tid = blockIdx.x * blockDim.x + threadIdx.x;
        int q = tid & 31;
        int b = (tid >> 5) & 31;
        int n = tid >> 10;
        float4 v;
        if (q < 16)
            v = in[(size_t)b * (NB * DD / 4) + n * (DD / 4) + q];
        else
            v = st[(size_t)b * (NB * HH / 4) + n * (HH / 4) + (q - 16)];
        size_t off = (size_t)n * ROWLEN + b * FF + q * 4;
        *(float4*)(g_X + off) = v;
        __half2 h0 = __floats2half2_rn(v.x, v.y);
        __half2 h1 = __floats2half2_rn(v.z, v.w);
        uint2 u;
        u.x = *(uint32_t*)&h0;
        u.y = *(uint32_t*)&h1;
        *(uint2*)(g_Xh + off) = u;
    } else {
        int i = (blockIdx.x - BUILD_BLOCKS) * blockDim.x + threadIdx.x;  // FF*OO
        int f = i & 127;
        int o = i >> 7;
        float w0 = w[(f * MM + 0) * OO + o];
        float w1 = w[(f * MM + 1) * OO + o];
        float w2 = w[(f * MM + 2) * OO + o];
        float w3 = w[(f * MM + 3) * OO + o];
        float w4 = w[(f * MM + 4) * OO + o];
        float p[5] = {w0 - w2 - w4, w1, 2.f * w2, w3, 2.f * w4};
#pragma unroll
        for (int m = 0; m < MM; m++) {
            __nv_bfloat16 hi = __float2bfloat16_rn(p[m]);
            float lo = p[m] - __bfloat162float(hi);
            size_t idx = ((size_t)m * OO + o) * FF + f;
            g_Wth[idx] = hi;
            g_Wtl[idx] = __float2bfloat16_rn(lo);
            g_Whf[idx] = __float2half_rn(p[m]);
        }
    }
}

// ---------------- SpMM: smem-staged edges, HFMA2 dual accumulators ----------------
#define ECHUNK 128

__global__ void __launch_bounds__(256) k_spmm(int stage) {
    __shared__ uint2 sedge[ECHUNK];                   // {col, half2(v)}
    const int n = blockIdx.x, s = blockIdx.y;
    const int col = blockIdx.z * 256 + threadIdx.x;   // uint4 index in row [0,512)
    const int srcm = (stage == 0) ? 0 : 1 + 2 * s;
    const int dstm = (stage == 0) ? 1 + 2 * s : 2 + 2 * s;
    const uint4* src = (const uint4*)(g_Xh + (size_t)srcm * NB * ROWLEN) + col;
    uint4* dst = (uint4*)(g_Xh + (size_t)dstm * NB * ROWLEN) + (size_t)n * 512 + col;
    const int e0  = g_off[s * (NB + 1) + n];
    const int end = g_off[s * (NB + 1) + n + 1];
    const float2* ep = g_edges + s * EE;

    __half2 accE[4], accO[4];
    const __half2 z2 = __floats2half2_rn(0.f, 0.f);
#pragma unroll
    for (int j = 0; j < 4; j++) { accE[j] = z2; accO[j] = z2; }

    for (int base = e0; base < end; base += ECHUNK) {
        const int cnt = min(ECHUNK, end - base);
        if (base > e0) __syncthreads();
        if (threadIdx.x < cnt) {
            float2 cv = ep[base + threadIdx.x];
            __half2 vh = __half2half2(__float2half_rn(cv.y));
            sedge[threadIdx.x] = make_uint2((uint32_t)__float_as_int(cv.x),
                                            *(uint32_t*)&vh);
        }
        __syncthreads();

        int i = 0;
        for (; i + 8 <= cnt; i += 8) {
            uint2 se[8];
#pragma unroll
            for (int k = 0; k < 8; k++) se[k] = sedge[i + k];
            uint4 r[8];
#pragma unroll
            for (int k = 0; k < 8; k++)
                r[k] = src[(size_t)se[k].x * 512];
#pragma unroll
            for (int k = 0; k < 8; k++) {
                __half2 vh = *(__half2*)&se[k].y;
                const __half2* h = (const __half2*)&r[k];
                __half2* acc = (k & 1) ? accO : accE;
#pragma unroll
                for (int j = 0; j < 4; j++)
                    acc[j] = __hfma2(vh, h[j], acc[j]);
            }
        }
        for (; i < cnt; i++) {
            uint2 se = sedge[i];
            uint4 r = src[(size_t)se.x * 512];
            __half2 vh = *(__half2*)&se.y;
            const __half2* h = (const __half2*)&r;
#pragma unroll
            for (int j = 0; j < 4; j++)
                accE[j] = __hfma2(vh, h[j], accE[j]);
        }
    }

    uint4 o;
    __half2* po = (__half2*)&o;
#pragma unroll
    for (int j = 0; j < 4; j++) {
        float2 fe = __half22float2(accE[j]);
        float2 fo = __half22float2(accO[j]);
        po[j] = __floats2half2_rn(fe.x + fo.x, fe.y + fo.y);
    }
    *dst = o;
}

// ---------------- GEMM: m=0 bf16x3, m=1..4 native fp16 MMA ----------------
#define BK   32
#define BKP  40
#define TSZ  (128 * BKP)
#define STG  (4 * TSZ)
#define GEMM_SMEM (2 * STG * 2)      // 81920 B

__device__ __forceinline__ void mma_bf16(float* c, const uint32_t* a, const uint32_t* b) {
    asm volatile(
        "mma.sync.aligned.m16n8k16.row.col.f32.bf16.bf16.f32 "
        "{%0,%1,%2,%3}, {%4,%5,%6,%7}, {%8,%9}, {%0,%1,%2,%3};\n"
        : "+f"(c[0]), "+f"(c[1]), "+f"(c[2]), "+f"(c[3])
        : "r"(a[0]), "r"(a[1]), "r"(a[2]), "r"(a[3]), "r"(b[0]), "r"(b[1]));
}
__device__ __forceinline__ void mma_f16(float* c, const uint32_t* a, const uint32_t* b) {
    asm volatile(
        "mma.sync.aligned.m16n8k16.row.col.f32.f16.f16.f32 "
        "{%0,%1,%2,%3}, {%4,%5,%6,%7}, {%8,%9}, {%0,%1,%2,%3};\n"
        : "+f"(c[0]), "+f"(c[1]), "+f"(c[2]), "+f"(c[3])
        : "r"(a[0]), "r"(a[1]), "r"(a[2]), "r"(a[3]), "r"(b[0]), "r"(b[1]));
}
__device__ __forceinline__ void ldsm_x4(uint32_t* r, uint32_t saddr) {
    asm volatile("ldmatrix.sync.aligned.m8n8.x4.shared.b16 {%0,%1,%2,%3}, [%4];"
                 : "=r"(r[0]), "=r"(r[1]), "=r"(r[2]), "=r"(r[3]) : "r"(saddr));
}

__global__ void __launch_bounds__(256) k_gemm_mma(const float* __restrict__ biases,
                                                  float* __restrict__ out) {
    extern __shared__ uint16_t smx[];   // [2][A|Al|B|Bl][128][BKP]
    const uint32_t smem0 = (uint32_t)__cvta_generic_to_shared(smx);

    const int t = threadIdx.x;
    const int wid = t >> 5, lane = t & 31;
    const int qr = lane >> 2, qc = lane & 3;
    const int wm = wid & 1, wn = wid >> 1;

    const int bn0 = blockIdx.x * 128;
    const int n0 = bn0 & (NB - 1);
    const int b  = bn0 >> 12;

    const int ar = t >> 1, ah = t & 1;   // A ldg: row, 16-elem half
    const int bo = t & 127, bp = t >> 7; // B ldg: o row, 16-elem part

    const int aRowOff = (wm * 64 + (lane & 15)) * BKP + ((lane >> 4) << 3);
    const int bRowOff = (wn * 32 + ((lane >> 4) << 3) + (lane & 7)) * BKP + (lane & 8);

    float acc[4][4][4];
#pragma unroll
    for (int i = 0; i < 4; i++)
#pragma unroll
        for (int j = 0; j < 4; j++)
#pragma unroll
            for (int k = 0; k < 4; k++) acc[i][j][k] = 0.f;

    float4 aRegF[4];                 // m=0: fp32 A
    uint4  aRegR[2];                 // m>=1: raw fp16 A
    uint4  bRegH[2], bRegL[2];       // m=0: bf16 hi/lo; m>=1: bRegH = fp16 W

    auto ldg_tile = [&](int kt) {
        const int m_ = kt >> 2, f0_ = (kt & 3) * BK;
        if (m_ == 0) {
            const float4* ap = (const float4*)(g_X +
                ((size_t)(n0 + ar) * BB + b) * FF + f0_ + ah * 16);
            aRegF[0] = ap[0]; aRegF[1] = ap[1]; aRegF[2] = ap[2]; aRegF[3] = ap[3];
            const uint4* bh = (const uint4*)(g_Wth + (size_t)bo * FF + f0_ + bp * 16);
            const uint4* bl = (const uint4*)(g_Wtl + (size_t)bo * FF + f0_ + bp * 16);
            bRegH[0] = bh[0]; bRegH[1] = bh[1];
            bRegL[0] = bl[0]; bRegL[1] = bl[1];
        } else {
            const uint4* apf = (const uint4*)(g_Xh +
                (((size_t)m_ * NB + (n0 + ar)) * BB + b) * FF + f0_ + ah * 16);
            aRegR[0] = apf[0]; aRegR[1] = apf[1];
            const uint4* bf = (const uint4*)(g_Whf + ((size_t)m_ * OO + bo) * FF +
                                             f0_ + bp * 16);
            bRegH[0] = bf[0]; bRegH[1] = bf[1];
        }
    };

    auto sts_tile = [&](int st, bool isM0) {
        uint16_t* Ah = smx + st * STG;
        uint16_t* Al = Ah + TSZ;
        uint16_t* Bh = Ah + 2 * TSZ;
        uint16_t* Bl = Ah + 3 * TSZ;
        if (isM0) {
            const float* av = (const float*)aRegF;
            uint32_t* AhR = (uint32_t*)(Ah + ar * BKP + ah * 16);
            uint32_t* AlR = (uint32_t*)(Al + ar * BKP + ah * 16);
#pragma unroll
            for (int j = 0; j < 8; j++) {
                float x0 = av[2 * j], x1 = av[2 * j + 1];
                __nv_bfloat16 h0 = __float2bfloat16_rn(x0);
                __nv_bfloat16 h1 = __float2bfloat16_rn(x1);
                __nv_bfloat16 l0 = __float2bfloat16_rn(x0 - __bfloat162float(h0));
                __nv_bfloat16 l1 = __float2bfloat16_rn(x1 - __bfloat162float(h1));
                __nv_bfloat162 hp; hp.x = h0; hp.y = h1;
                __nv_bfloat162 lp; lp.x = l0; lp.y = l1;
                AhR[j] = *(uint32_t*)&hp;
                AlR[j] = *(uint32_t*)&lp;
            }
            uint32_t* BhR = (uint32_t*)(Bh + bo * BKP + bp * 16);
            uint32_t* BlR = (uint32_t*)(Bl + bo * BKP + bp * 16);
            const uint32_t* bhv = (const uint32_t*)bRegH;
            const uint32_t* blv = (const uint32_t*)bRegL;
#pragma unroll
            for (int j = 0; j < 8; j++) { BhR[j] = bhv[j]; BlR[j] = blv[j]; }
        } else {
            uint4* Ar = (uint4*)(Ah + ar * BKP + ah * 16);
            Ar[0] = aRegR[0]; Ar[1] = aRegR[1];
            uint4* Br = (uint4*)(Bh + bo * BKP + bp * 16);
            Br[0] = bRegH[0]; Br[1] = bRegH[1];
        }
    };

    ldg_tile(0);
    sts_tile(0, true);
    __syncthreads();

    for (int kt = 0; kt < 20; kt++) {
        const int st = kt & 1;
        if (kt < 19) ldg_tile(kt + 1);

        const uint32_t baseAh = smem0 + (st * STG) * 2;
        const uint32_t baseAl = baseAh + TSZ * 2;
        const uint32_t baseBh = baseAh + 2 * TSZ * 2;
        const uint32_t baseBl = baseAh + 3 * TSZ * 2;

        if (kt < 4) {
            // m=0 slab: bf16 hi/lo x3
#pragma unroll
            for (int kk = 0; kk < BK; kk += 16) {
                uint32_t fbh[4][2], fbl[4][2];
#pragma unroll
                for (int p = 0; p < 2; p++) {
                    uint32_t r[4];
                    uint32_t off = (bRowOff + p * 16 * BKP + kk) * 2;
                    ldsm_x4(r, baseBh + off);
                    fbh[2 * p][0] = r[0]; fbh[2 * p][1] = r[1];
                    fbh[2 * p + 1][0] = r[2]; fbh[2 * p + 1][1] = r[3];
                    ldsm_x4(r, baseBl + off);
                    fbl[2 * p][0] = r[0]; fbl[2 * p][1] = r[1];
                    fbl[2 * p + 1][0] = r[2]; fbl[2 * p + 1][1] = r[3];
                }
#pragma unroll
                for (int mi = 0; mi < 4; mi++) {
                    uint32_t fah[4], fal[4];
                    uint32_t off = (aRowOff + mi * 16 * BKP + kk) * 2;
                    ldsm_x4(fah, baseAh + off);
                    ldsm_x4(fal, baseAl + off);
#pragma unroll
                    for (int ni = 0; ni < 4; ni++) {
                        mma_bf16(acc[mi][ni], fah, fbh[ni]);
                        mma_bf16(acc[mi][ni], fah, fbl[ni]);
                        mma_bf16(acc[mi][ni], fal, fbh[ni]);
                    }
                }
            }
        } else {
            // m>=1 slabs: single native fp16 MMA
#pragma unroll
            for (int kk = 0; kk < BK; kk += 16) {
                uint32_t fb[4][2];
#pragma unroll
                for (int p = 0; p < 2; p++) {
                    uint32_t r[4];
                    uint32_t off = (bRowOff + p * 16 * BKP + kk) * 2;
                    ldsm_x4(r, baseBh + off);
                    fb[2 * p][0] = r[0]; fb[2 * p][1] = r[1];
                    fb[2 * p + 1][0] = r[2]; fb[2 * p + 1][1] = r[3];
                }
#pragma unroll
                for (int mi = 0; mi < 4; mi++) {
                    uint32_t fa[4];
                    uint32_t off = (aRowOff + mi * 16 * BKP + kk) * 2;
                    ldsm_x4(fa, baseAh + off);
#pragma unroll
                    for (int ni = 0; ni < 4; ni++)
                        mma_f16(acc[mi][ni], fa, fb[ni]);
                }
            }
        }

        if (kt < 19) sts_tile(1 - st, (kt + 1) < 4);
        __syncthreads();
    }

#pragma unroll
    for (int mi = 0; mi < 4; mi++) {
#pragma unroll
        for (int ni = 0; ni < 4; ni++) {
            int col = wn * 32 + ni * 8 + 2 * qc;
            float b0 = biases[col], b1 = biases[col + 1];
            int r0 = bn0 + wm * 64 + mi * 16 + qr;
            float2 v0 = make_float2(acc[mi][ni][0] + b0, acc[mi][ni][1] + b1);
            float2 v1 = make_float2(acc[mi][ni][2] + b0, acc[mi][ni][3] + b1);
            *(float2*)(out + (size_t)r0 * OO + col)       = v0;
            *(float2*)(out + (size_t)(r0 + 8) * OO + col) = v1;
        }
    }
}

// ---------------- launch (serial) ----------------
extern "C" void kernel_launch(void* const* d_in, const int* in_sizes, int n_in,
                              void* d_out, int out_size) {
    const float* inputs = (const float*)d_in[0];
    const float* state  = (const float*)d_in[1];
    const int*   rows   = (const int*)d_in[2];
    const int*   cols   = (const int*)d_in[3];
    const float* vals   = (const float*)d_in[4];
    const float* weight = (const float*)d_in[5];
    const float* biases = (const float*)d_in[6];
    float* out = (float*)d_out;
    (void)in_sizes; (void)n_in; (void)out_size;

    cudaFuncSetAttribute(k_gemm_mma, cudaFuncAttributeMaxDynamicSharedMemorySize,
                         GEMM_SMEM);

    k_zero_cnt<<<(SS * NB + 255) / 256, 256>>>();
    k_histo<<<(SS * EE) / 256, 256>>>(rows);
    k_scan<<<SS, 1024>>>();
    k_scatter<<<(SS * EE) / 256, 256>>>(rows, cols, vals);
    k_buildprep<<<BUILD_BLOCKS + (FF * OO) / 256, 256>>>((const float4*)inputs,
                                                         (const float4*)state, weight);
    k_spmm<<<dim3(NB, SS, 2), 256>>>(0);
    k_spmm<<<dim3(NB, SS, 2), 256>>>(1);
    k_gemm_mma<<<(BB * NB) / 128, 256, GEMM_SMEM>>>(biases, out);
}

// round 12
// speedup vs baseline: 2.9605x; 1.0612x over previous
#include <cuda_runtime.h>
#include <cuda_fp16.h>
#include <cstdint>

// DiffusionGraphConv — GB300 sm_103 (baseline PTX; no tcgen05 in this toolchain)
// Serial pipeline (overlap falsified R7-R9; SpMM at L2-BW ceiling R5/R6/R10).
//   1) CSR build                                    ~25us
//   2) X0h build (fp16) + fp16 weight fold          ~15us
//   3) SpMM x2 (smem edges, HFMA2)                  ~258us (L2-BW floor)
//   4) GEMM all-fp16 MMA: m=0 A hi/lo x2, m>=1 x1   ~38us
// A for m=0 read directly from inputs/state (g_X fp32 mirror deleted).

#define NB 4096
#define BB 32
#define DD 64
#define HH 64
#define FF 128
#define EE 65536
#define SS 2
#define MM 5
#define OO 128
#define ROWLEN (BB * FF)

// ---- device scratch ----
__device__ __half g_Xh[(size_t)MM * NB * ROWLEN];      // [X0h,Y0,Z0,Y1,Z1] fp16
__device__ float2 g_edges[SS * EE];
__device__ int    g_off[SS * (NB + 1)];
__device__ int    g_cur[SS * NB];
__device__ int    g_cnt[SS * NB];
__device__ __half g_Whf[MM * OO * FF];                 // folded, transposed [m][o][f] fp16

// ---------------- CSR build ----------------
__global__ void k_zero_cnt() {
    int i = blockIdx.x * blockDim.x + threadIdx.x;
    if (i < SS * NB) g_cnt[i] = 0;
}
__global__ void k_histo(const int* __restrict__ rows) {
    int i = blockIdx.x * blockDim.x + threadIdx.x;
    int s = i >> 16;
    atomicAdd(&g_cnt[s * NB + rows[i]], 1);
}
__global__ void k_scan() {
    int s = blockIdx.x;
    int t = threadIdx.x;
    __shared__ int wsum[32];
    int base = s * NB + t * 4;
    int v0 = g_cnt[base + 0], v1 = g_cnt[base + 1];
    int v2 = g_cnt[base + 2], v3 = g_cnt[base + 3];
    int tot = v0 + v1 + v2 + v3;
    int lane = t & 31, w = t >> 5;
    int x = tot;
#pragma unroll
    for (int d = 1; d < 32; d <<= 1) {
        int y = __shfl_up_sync(0xffffffffu, x, d);
        if (lane >= d) x += y;
    }
    if (lane == 31) wsum[w] = x;
    __syncthreads();
    if (w == 0) {
        int y = wsum[lane];
#pragma unroll
        for (int d = 1; d < 32; d <<= 1) {
            int z = __shfl_up_sync(0xffffffffu, y, d);
            if (lane >= d) y += z;
        }
        wsum[lane] = y;
    }
    __syncthreads();
    int excl = x - tot + (w > 0 ? wsum[w - 1] : 0);
    int ob = s * (NB + 1) + t * 4;
    g_off[ob + 0] = excl;
    g_off[ob + 1] = excl + v0;
    g_off[ob + 2] = excl + v0 + v1;
    g_off[ob + 3] = excl + v0 + v1 + v2;
    g_cur[base + 0] = excl;
    g_cur[base + 1] = excl + v0;
    g_cur[base + 2] = excl + v0 + v1;
    g_cur[base + 3] = excl + v0 + v1 + v2;
    if (t == 1023) g_off[s * (NB + 1) + NB] = excl + tot;
}
__global__ void k_scatter(const int* __restrict__ rows, const int* __restrict__ cols,
                          const float* __restrict__ vals) {
    int i = blockIdx.x * blockDim.x + threadIdx.x;
    int s = i >> 16;
    int r = rows[i];
    int p = atomicAdd(&g_cur[s * NB + r], 1);
    g_edges[s * EE + p] = make_float2(__int_as_float(cols[i]), vals[i]);
}

// ---------------- X0h build + fp16 weight fold (merged) ----------------
#define BUILD_BLOCKS ((NB * BB * 32) / 256)
__global__ void k_buildprep(const float4* __restrict__ in, const float4* __restrict__ st,
                            const float* __restrict__ w) {
    if (blockIdx.x < BUILD_BLOCKS) {
        int tid = blockIdx.x * blockDim.x + threadIdx.x;
        int q = tid & 31;
        int b = (tid >> 5) & 31;
        int n = tid >> 10;
        float4 v;
        if (q < 16)
            v = in[(size_t)b * (NB * DD / 4) + n * (DD / 4) + q];
        else
            v = st[(size_t)b * (NB * HH / 4) + n * (HH / 4) + (q - 16)];
        size_t off = (size_t)n * ROWLEN + b * FF + q * 4;
        __half2 h0 = __floats2half2_rn(v.x, v.y);
        __half2 h1 = __floats2half2_rn(v.z, v.w);
        uint2 u;
        u.x = *(uint32_t*)&h0;
        u.y = *(uint32_t*)&h1;
        *(uint2*)(g_Xh + off) = u;
    } else {
        int i = (blockIdx.x - BUILD_BLOCKS) * blockDim.x + threadIdx.x;  // FF*OO
        int f = i & 127;
        int o = i >> 7;
        float w0 = w[(f * MM + 0) * OO + o];
        float w1 = w[(f * MM + 1) * OO + o];
        float w2 = w[(f * MM + 2) * OO + o];
        float w3 = w[(f * MM + 3) * OO + o];
        float w4 = w[(f * MM + 4) * OO + o];
        float p[5] = {w0 - w2 - w4, w1, 2.f * w2, w3, 2.f * w4};
#pragma unroll
        for (int m = 0; m < MM; m++)
            g_Whf[((size_t)m * OO + o) * FF + f] = __float2half_rn(p[m]);
    }
}

// ---------------- SpMM: smem-staged edges, HFMA2 dual accumulators ----------------
#define ECHUNK 128

__global__ void __launch_bounds__(256) k_spmm(int stage) {
    __shared__ uint2 sedge[ECHUNK];                   // {col, half2(v)}
    const int n = blockIdx.x, s = blockIdx.y;
    const int col = blockIdx.z * 256 + threadIdx.x;   // uint4 index in row [0,512)
    const int srcm = (stage == 0) ? 0 : 1 + 2 * s;
    const int dstm = (stage == 0) ? 1 + 2 * s : 2 + 2 * s;
    const uint4* src = (const uint4*)(g_Xh + (size_t)srcm * NB * ROWLEN) + col;
    uint4* dst = (uint4*)(g_Xh + (size_t)dstm * NB * ROWLEN) + (size_t)n * 512 + col;
    const int e0  = g_off[s * (NB + 1) + n];
    const int end = g_off[s * (NB + 1) + n + 1];
    const float2* ep = g_edges + s * EE;

    __half2 accE[4], accO[4];
    const __half2 z2 = __floats2half2_rn(0.f, 0.f);
#pragma unroll
    for (int j = 0; j < 4; j++) { accE[j] = z2; accO[j] = z2; }

    for (int base = e0; base < end; base += ECHUNK) {
        const int cnt = min(ECHUNK, end - base);
        if (base > e0) __syncthreads();
        if (threadIdx.x < cnt) {
            float2 cv = ep[base + threadIdx.x];
            __half2 vh = __half2half2(__float2half_rn(cv.y));
            sedge[threadIdx.x] = make_uint2((uint32_t)__float_as_int(cv.x),
                                            *(uint32_t*)&vh);
        }
        __syncthreads();

        int i = 0;
        for (; i + 8 <= cnt; i += 8) {
            uint2 se[8];
#pragma unroll
            for (int k = 0; k < 8; k++) se[k] = sedge[i + k];
            uint4 r[8];
#pragma unroll
            for (int k = 0; k < 8; k++)
                r[k] = src[(size_t)se[k].x * 512];
#pragma unroll
            for (int k = 0; k < 8; k++) {
                __half2 vh = *(__half2*)&se[k].y;
                const __half2* h = (const __half2*)&r[k];
                __half2* acc = (k & 1) ? accO : accE;
#pragma unroll
                for (int j = 0; j < 4; j++)
                    acc[j] = __hfma2(vh, h[j], acc[j]);
            }
        }
        for (; i < cnt; i++) {
            uint2 se = sedge[i];
            uint4 r = src[(size_t)se.x * 512];
            __half2 vh = *(__half2*)&se.y;
            const __half2* h = (const __half2*)&r;
#pragma unroll
            for (int j = 0; j < 4; j++)
                accE[j] = __hfma2(vh, h[j], accE[j]);
        }
    }

    uint4 o;
    __half2* po = (__half2*)&o;
#pragma unroll
    for (int j = 0; j < 4; j++) {
        float2 fe = __half22float2(accE[j]);
        float2 fo = __half22float2(accO[j]);
        po[j] = __floats2half2_rn(fe.x + fo.x, fe.y + fo.y);
    }
    *dst = o;
}

// ---------------- GEMM: all fp16 MMA; m=0 A hi/lo x2, m>=1 x1 ----------------
#define BK   32
#define BKP  40
#define TSZ  (128 * BKP)
#define STG3 (3 * TSZ)               // tiles: A(hi) | A(lo) | B
#define GEMM_SMEM (2 * STG3 * 2)     // 61440 B

__device__ __forceinline__ void mma_f16(float* c, const uint32_t* a, const uint32_t* b) {
    asm volatile(
        "mma.sync.aligned.m16n8k16.row.col.f32.f16.f16.f32 "
        "{%0,%1,%2,%3}, {%4,%5,%6,%7}, {%8,%9}, {%0,%1,%2,%3};\n"
        : "+f"(c[0]), "+f"(c[1]), "+f"(c[2]), "+f"(c[3])
        : "r"(a[0]), "r"(a[1]), "r"(a[2]), "r"(a[3]), "r"(b[0]), "r"(b[1]));
}
__device__ __forceinline__ void ldsm_x4(uint32_t* r, uint32_t saddr) {
    asm volatile("ldmatrix.sync.aligned.m8n8.x4.shared.b16 {%0,%1,%2,%3}, [%4];"
                 : "=r"(r[0]), "=r"(r[1]), "=r"(r[2]), "=r"(r[3]) : "r"(saddr));
}

__global__ void __launch_bounds__(256) k_gemm_mma(const float* __restrict__ inputs,
                                                  const float* __restrict__ state,
                                                  const float* __restrict__ biases,
                                                  float* __restrict__ out) {
    extern __shared__ uint16_t smx[];   // [2][Ah|Al|B][128][BKP]
    const uint32_t smem0 = (uint32_t)__cvta_generic_to_shared(smx);

    const int t = threadIdx.x;
    const int wid = t >> 5, lane = t & 31;
    const int qr = lane >> 2, qc = lane & 3;
    const int wm = wid & 1, wn = wid >> 1;

    const int bn0 = blockIdx.x * 128;
    const int n0 = bn0 & (NB - 1);
    const int b  = bn0 >> 12;

    const int ar = t >> 1, ah = t & 1;   // A ldg: row, 16-elem half
    const int bo = t & 127, bp = t >> 7; // B ldg: o row, 16-elem part

    const int aRowOff = (wm * 64 + (lane & 15)) * BKP + ((lane >> 4) << 3);
    const int bRowOff = (wn * 32 + ((lane >> 4) << 3) + (lane & 7)) * BKP + (lane & 8);

    float acc[4][4][4];
#pragma unroll
    for (int i = 0; i < 4; i++)
#pragma unroll
        for (int j = 0; j < 4; j++)
#pragma unroll
            for (int k = 0; k < 4; k++) acc[i][j][k] = 0.f;

    float4 aRegF[4];                 // m=0: fp32 A (from inputs/state)
    uint4  aRegR[2];                 // m>=1: raw fp16 A
    uint4  bReg[2];                  // fp16 W

    auto ldg_tile = [&](int kt) {
        const int m_ = kt >> 2, f0_ = (kt & 3) * BK;
        if (m_ == 0) {
            const int fseg = f0_ + ah * 16;           // {0,16,...,112}
            const float* src = (fseg < DD)
                ? inputs + ((size_t)b * NB + (n0 + ar)) * DD + fseg
                : state  + ((size_t)b * NB + (n0 + ar)) * HH + (fseg - DD);
            const float4* ap = (const float4*)src;
            aRegF[0] = ap[0]; aRegF[1] = ap[1]; aRegF[2] = ap[2]; aRegF[3] = ap[3];
        } else {
            const uint4* apf = (const uint4*)(g_Xh +
                (((size_t)m_ * NB + (n0 + ar)) * BB + b) * FF + f0_ + ah * 16);
            aRegR[0] = apf[0]; aRegR[1] = apf[1];
        }
        const uint4* bf = (const uint4*)(g_Whf + ((size_t)m_ * OO + bo) * FF +
                                         f0_ + bp * 16);
        bReg[0] = bf[0]; bReg[1] = bf[1];
    };

    auto sts_tile = [&](int st, bool isM0) {
        uint16_t* Ah = smx + st * STG3;
        uint16_t* Al = Ah + TSZ;
        uint16_t* Bt = Ah + 2 * TSZ;
        if (isM0) {
            const float* av = (const float*)aRegF;
            uint32_t* AhR = (uint32_t*)(Ah + ar * BKP + ah * 16);
            uint32_t* AlR = (uint32_t*)(Al + ar * BKP + ah * 16);
#pragma unroll
            for (int j = 0; j < 8; j++) {
                float x0 = av[2 * j], x1 = av[2 * j + 1];
                __half h0 = __float2half_rn(x0);
                __half h1 = __float2half_rn(x1);
                __half l0 = __float2half_rn(x0 - __half2float(h0));
                __half l1 = __float2half_rn(x1 - __half2float(h1));
                __half2 hp; hp.x = h0; hp.y = h1;
                __half2 lp; lp.x = l0; lp.y = l1;
                AhR[j] = *(uint32_t*)&hp;
                AlR[j] = *(uint32_t*)&lp;
            }
        } else {
            uint4* Ar = (uint4*)(Ah + ar * BKP + ah * 16);
            Ar[0] = aRegR[0]; Ar[1] = aRegR[1];
        }
        uint4* Br = (uint4*)(Bt + bo * BKP + bp * 16);
        Br[0] = bReg[0]; Br[1] = bReg[1];
    };

    ldg_tile(0);
    sts_tile(0, true);
    __syncthreads();

    for (int kt = 0; kt < 20; kt++) {
        const int st = kt & 1;
        if (kt < 19) ldg_tile(kt + 1);

        const uint32_t baseAh = smem0 + (st * STG3) * 2;
        const uint32_t baseAl = baseAh + TSZ * 2;
        const uint32_t baseB  = baseAh + 2 * TSZ * 2;

        if (kt < 4) {
            // m=0 slab: fp16 hi/lo x2
#pragma unroll
            for (int kk = 0; kk < BK; kk += 16) {
                uint32_t fb[4][2];
#pragma unroll
                for (int p = 0; p < 2; p++) {
                    uint32_t r[4];
                    uint32_t off = (bRowOff + p * 16 * BKP + kk) * 2;
                    ldsm_x4(r, baseB + off);
                    fb[2 * p][0] = r[0]; fb[2 * p][1] = r[1];
                    fb[2 * p + 1][0] = r[2]; fb[2 * p + 1][1] = r[3];
                }
#pragma unroll
                for (int mi = 0; mi < 4; mi++) {
                    uint32_t fah[4], fal[4];
                    uint32_t off = (aRowOff + mi * 16 * BKP + kk) * 2;
                    ldsm_x4(fah, baseAh + off);
                    ldsm_x4(fal, baseAl + off);
#pragma unroll
                    for (int ni = 0; ni < 4; ni++) {
                        mma_f16(acc[mi][ni], fah, fb[ni]);
                        mma_f16(acc[mi][ni], fal, fb[ni]);
                    }
                }
            }
        } else {
            // m>=1 slabs: single fp16 MMA
#pragma unroll
            for (int kk = 0; kk < BK; kk += 16) {
                uint32_t fb[4][2];
#pragma unroll
                for (int p = 0; p < 2; p++) {
                    uint32_t r[4];
                    uint32_t off = (bRowOff + p * 16 * BKP + kk) * 2;
                    ldsm_x4(r, baseB + off);
                    fb[2 * p][0] = r[0]; fb[2 * p][1] = r[1];
                    fb[2 * p + 1][0] = r[2]; fb[2 * p + 1][1] = r[3];
                }
#pragma unroll
                for (int mi = 0; mi < 4; mi++) {
                    uint32_t fa[4];
                    uint32_t off = (aRowOff + mi * 16 * BKP + kk) * 2;
                    ldsm_x4(fa, baseAh + off);
#pragma unroll
                    for (int ni = 0; ni < 4; ni++)
                        mma_f16(acc[mi][ni], fa, fb[ni]);
                }
            }
        }

        if (kt < 19) sts_tile(1 - st, (kt + 1) < 4);
        __syncthreads();
    }

#pragma unroll
    for (int mi = 0; mi < 4; mi++) {
#pragma unroll
        for (int ni = 0; ni < 4; ni++) {
            int col = wn * 32 + ni * 8 + 2 * qc;
            float b0 = biases[col], b1 = biases[col + 1];
            int r0 = bn0 + wm * 64 + mi * 16 + qr;
            float2 v0 = make_float2(acc[mi][ni][0] + b0, acc[mi][ni][1] + b1);
            float2 v1 = make_float2(acc[mi][ni][2] + b0, acc[mi][ni][3] + b1);
            *(float2*)(out + (size_t)r0 * OO + col)       = v0;
            *(float2*)(out + (size_t)(r0 + 8) * OO + col) = v1;
        }
    }
}

// ---------------- launch (serial) ----------------
extern "C" void kernel_launch(void* const* d_in, const int* in_sizes, int n_in,
                              void* d_out, int out_size) {
    const float* inputs = (const float*)d_in[0];
    const float* state  = (const float*)d_in[1];
    const int*   rows   = (const int*)d_in[2];
    const int*   cols   = (const int*)d_in[3];
    const float* vals   = (const float*)d_in[4];
    const float* weight = (const float*)d_in[5];
    const float* biases = (const float*)d_in[6];
    float* out = (float*)d_out;
    (void)in_sizes; (void)n_in; (void)out_size;

    cudaFuncSetAttribute(k_gemm_mma, cudaFuncAttributeMaxDynamicSharedMemorySize,
                         GEMM_SMEM);

    k_zero_cnt<<<(SS * NB + 255) / 256, 256>>>();
    k_histo<<<(SS * EE) / 256, 256>>>(rows);
    k_scan<<<SS, 1024>>>();
    k_scatter<<<(SS * EE) / 256, 256>>>(rows, cols, vals);
    k_buildprep<<<BUILD_BLOCKS + (FF * OO) / 256, 256>>>((const float4*)inputs,
                                                         (const float4*)state, weight);
    k_spmm<<<dim3(NB, SS, 2), 256>>>(0);
    k_spmm<<<dim3(NB, SS, 2), 256>>>(1);
    k_gemm_mma<<<(BB * NB) / 128, 256, GEMM_SMEM>>>(inputs, state, biases, out);
}